// round 15
// baseline (speedup 1.0000x reference)
#include <cuda_runtime.h>
#include <cuda_bf16.h>
#include <cuda_fp16.h>

// ---------------------------------------------------------------------------
// CNN_ODE: conv1d+SiLU (reg-resident x, fp16 output) -> enc1 fp16 mma
// (double-buffered) -> enc2 -> 50-step dopri5 (fp16 mma ODE) -> regressor.
// B = 65536.
// ---------------------------------------------------------------------------

#define SEQ   40
#define INC   24
#define NK    36
#define FLAT  1440
#define HID   64
#define STEPS 50

__device__ float g_theta0[HID * 65536];   // [dim][sample], fp32

__device__ __forceinline__ float tanhap(float x) {
    float r; asm("tanh.approx.f32 %0,%1;" : "=f"(r) : "f"(x)); return r;
}
__device__ __forceinline__ void mma_fp16(
    float (&c)[4], const unsigned (&a)[4], unsigned b0, unsigned b1)
{
    asm("mma.sync.aligned.m16n8k16.row.col.f32.f16.f16.f32 "
        "{%0,%1,%2,%3},{%4,%5,%6,%7},{%8,%9},{%0,%1,%2,%3};"
        : "+f"(c[0]), "+f"(c[1]), "+f"(c[2]), "+f"(c[3])
        : "r"(a[0]), "r"(a[1]), "r"(a[2]), "r"(a[3]), "r"(b0), "r"(b1));
}
__device__ __forceinline__ unsigned pkh2(float a, float b) {
    __half2 h = __floats2half2_rn(a, b);
    return *reinterpret_cast<unsigned*>(&h);
}

// ============================== Encoder ====================================
// 32 samples/CTA, 256 threads.  sC: fp16 [32][1448 halves] (724 words/row).
// sW: fp16 chunks [128][40 halves] (20 words/row), double buffered.
#define ENC_SPB 32
#define SCW     724                    // sC row stride in words
#define SWW     20                     // weight chunk row stride in words
#define SH1ST   132
#define NCHUNK  (FLAT / 32)            // 45
#define ENC_SC_WORDS (ENC_SPB * SCW)           // 23168
#define ENC_SMEM_BYTES ((ENC_SC_WORDS + 2 * 128 * SWW) * 4)   // 113152

__global__ void __launch_bounds__(256, 2) enc_kernel(
    const float* __restrict__ x,
    const float* __restrict__ conv_w, const float* __restrict__ conv_b,
    const float* __restrict__ enc1_w, const float* __restrict__ enc1_b,
    const float* __restrict__ enc2_w, const float* __restrict__ enc2_b,
    int B)
{
    extern __shared__ unsigned smu[];
    unsigned* sC  = smu;                              // fp16 conv out (words)
    unsigned* sW0 = sC + ENC_SC_WORDS;                // weight buf 0
    unsigned* sW1 = sW0 + 128 * SWW;                  // weight buf 1
    float*    sH1 = (float*)sC;                       // [32][132] (aliases sC)
    float*    scw = (float*)sW0;                      // conv weights (2592 f)

    const int tid = threadIdx.x;
    const long long blk = blockIdx.x;

    for (int i = tid; i < NK * 72; i += 256) scw[i] = conv_w[i];
    __syncthreads();

    // ---- conv1d (pad=1) + SiLU -> sC fp16.  thread = (sample, 5 s-pos).
    // k in groups of 2; x halo reloaded per (kg, c-half) from L1.
    {
        const int sp = tid >> 3;
        const int sq = tid & 7;
        const float* xs = x + (blk * ENC_SPB + sp) * (SEQ * INC);
        __half* sCh = (__half*)(sC) + sp * (2 * SCW);

        for (int kg = 0; kg < 18; kg++) {
            float acc[2][5];
#pragma unroll
            for (int j = 0; j < 2; j++) {
                const float bk = __ldg(&conv_b[kg * 2 + j]);
#pragma unroll
                for (int i = 0; i < 5; i++) acc[j][i] = bk;
            }
#pragma unroll
            for (int ch = 0; ch < 2; ch++) {
                const int c0 = ch * 12;
                float xr[7][12];
#pragma unroll
                for (int r = 0; r < 7; r++) {
                    const int s = sq * 5 - 1 + r;
                    if (s >= 0 && s < SEQ) {
                        const float4 v0 = __ldg((const float4*)(xs + s * INC + c0));
                        const float4 v1 = __ldg((const float4*)(xs + s * INC + c0 + 4));
                        const float4 v2 = __ldg((const float4*)(xs + s * INC + c0 + 8));
                        xr[r][0]=v0.x; xr[r][1]=v0.y; xr[r][2]=v0.z; xr[r][3]=v0.w;
                        xr[r][4]=v1.x; xr[r][5]=v1.y; xr[r][6]=v1.z; xr[r][7]=v1.w;
                        xr[r][8]=v2.x; xr[r][9]=v2.y; xr[r][10]=v2.z; xr[r][11]=v2.w;
                    } else {
#pragma unroll
                        for (int cc = 0; cc < 12; cc++) xr[r][cc] = 0.0f;
                    }
                }
#pragma unroll
                for (int j = 0; j < 2; j++) {
                    const int k = kg * 2 + j;
#pragma unroll
                    for (int cc = 0; cc < 12; cc++) {
                        const float w0 = scw[k * 72 + (c0 + cc) * 3 + 0];
                        const float w1 = scw[k * 72 + (c0 + cc) * 3 + 1];
                        const float w2 = scw[k * 72 + (c0 + cc) * 3 + 2];
#pragma unroll
                        for (int i = 0; i < 5; i++) {
                            acc[j][i] = fmaf(w0, xr[i][cc],     acc[j][i]);
                            acc[j][i] = fmaf(w1, xr[i + 1][cc], acc[j][i]);
                            acc[j][i] = fmaf(w2, xr[i + 2][cc], acc[j][i]);
                        }
                    }
                }
            }
#pragma unroll
            for (int j = 0; j < 2; j++)
#pragma unroll
                for (int i = 0; i < 5; i++) {
                    const float v  = acc[j][i];
                    const float sg = fmaf(0.5f, tanhap(0.5f * v), 0.5f);
                    sCh[(kg * 2 + j) * SEQ + sq * 5 + i] = __float2half_rn(v * sg);
                }
        }
    }
    __syncthreads();

    // ---- enc1 via fp16 mma: C[32 samp][128 out], K=1440, double-buffered ----
    const int w    = tid >> 5;
    const int lane = tid & 31;
    const int g    = lane >> 2;
    const int tig  = lane & 3;
    const int mh   = w & 1;
    const int nq   = w >> 1;
    const int srow = mh * 16 + g;
    const int nbase = nq * 32;

    float c[4][4];
#pragma unroll
    for (int nt = 0; nt < 4; nt++) {
        const int n0 = nbase + nt * 8 + 2 * tig;
        c[nt][0] = __ldg(&enc1_b[n0]);
        c[nt][1] = __ldg(&enc1_b[n0 + 1]);
        c[nt][2] = c[nt][0];
        c[nt][3] = c[nt][1];
    }

    // staging: 32 fp32 per row -> 16 words fp16; 4 float4 per thread per chunk
    float4 pre[4];
#pragma unroll
    for (int j = 0; j < 4; j++) {
        const int f  = tid + j * 256;
        const int oc = f >> 3, qd = f & 7;
        pre[j] = __ldg((const float4*)(enc1_w + (size_t)oc * FLAT + qd * 4));
    }

    for (int kci = 0; kci < NCHUNK; kci++) {
        unsigned* buf = (kci & 1) ? sW1 : sW0;
#pragma unroll
        for (int j = 0; j < 4; j++) {
            const int f  = tid + j * 256;
            const int oc = f >> 3, qd = f & 7;
            uint2 u;
            u.x = pkh2(pre[j].x, pre[j].y);
            u.y = pkh2(pre[j].z, pre[j].w);
            *(uint2*)(buf + oc * SWW + qd * 2) = u;
        }
        if (kci + 1 < NCHUNK) {
            const int kc = (kci + 1) * 32;
#pragma unroll
            for (int j = 0; j < 4; j++) {
                const int f  = tid + j * 256;
                const int oc = f >> 3, qd = f & 7;
                pre[j] = __ldg((const float4*)(enc1_w + (size_t)oc * FLAT + kc + qd * 4));
            }
        }
        __syncthreads();
        const int kw = kci * 16;               // chunk base in words
#pragma unroll
        for (int kt = 0; kt < 2; kt++) {
            unsigned a[4];
            const unsigned* ar = sC + srow * SCW + kw + kt * 8 + tig;
            a[0] = ar[0];
            a[1] = ar[8 * SCW];
            a[2] = ar[4];
            a[3] = ar[8 * SCW + 4];
#pragma unroll
            for (int nt = 0; nt < 4; nt++) {
                const unsigned* br = buf + (nbase + nt * 8 + g) * SWW + kt * 8 + tig;
                mma_fp16(c[nt], a, br[0], br[4]);
            }
        }
    }
    __syncthreads();   // all mma reads of sC done -> sH1 may overwrite it

#pragma unroll
    for (int nt = 0; nt < 4; nt++) {
        const int n0 = nbase + nt * 8 + 2 * tig;
        sH1[srow * SH1ST + n0]           = fmaxf(c[nt][0], 0.0f);
        sH1[srow * SH1ST + n0 + 1]       = fmaxf(c[nt][1], 0.0f);
        sH1[(srow + 8) * SH1ST + n0]     = fmaxf(c[nt][2], 0.0f);
        sH1[(srow + 8) * SH1ST + n0 + 1] = fmaxf(c[nt][3], 0.0f);
    }
    __syncthreads();

    // ---- enc2: [128 -> 64] -> g_theta0 transposed [dim][sample] ----
    for (int t = tid; t < ENC_SPB * HID; t += 256) {
        const int oc = t >> 5;
        const int sp = t & 31;
        float acc = __ldg(&enc2_b[oc]);
        const float* wr = enc2_w + oc * 128;
        const float* hv = sH1 + sp * SH1ST;
#pragma unroll
        for (int i = 0; i < 128; i += 4) {
            const float4 wv = __ldg((const float4*)(wr + i));
            const float4 h4 = *(const float4*)(hv + i);
            acc = fmaf(wv.x, h4.x, fmaf(wv.y, h4.y, fmaf(wv.z, h4.z, fmaf(wv.w, h4.w, acc))));
        }
        g_theta0[(size_t)oc * B + blk * ENC_SPB + sp] = acc;
    }
}

// ================================ ODE (unchanged R14) =======================
#define ODE_SPB 16
#define KW 36

__device__ __forceinline__ void gemm16h(
    const unsigned (&A)[4][4], const unsigned* __restrict__ sIn,
    float blo, float bhi, int g, int tig, float (&c)[2][4])
{
#pragma unroll
    for (int nt = 0; nt < 2; nt++) {
        c[nt][0] = blo; c[nt][1] = blo; c[nt][2] = bhi; c[nt][3] = bhi;
    }
#pragma unroll
    for (int kt = 0; kt < 4; kt++) {
#pragma unroll
        for (int nt = 0; nt < 2; nt++) {
            const unsigned* r = sIn + (nt * 8 + g) * KW + kt * 8 + tig;
            mma_fp16(c[nt], A[kt], r[0], r[4]);
        }
    }
}

__device__ __forceinline__ void store_frag_h(
    unsigned* __restrict__ dst, const float (&c)[2][4], int m0, int tig)
{
    __half* d = (__half*)dst;
#pragma unroll
    for (int nt = 0; nt < 2; nt++) {
        const int n0 = nt * 8 + 2 * tig;
        d[(n0)     * (2*KW) + m0]     = __float2half_rn(c[nt][0]);
        d[(n0 + 1) * (2*KW) + m0]     = __float2half_rn(c[nt][1]);
        d[(n0)     * (2*KW) + m0 + 8] = __float2half_rn(c[nt][2]);
        d[(n0 + 1) * (2*KW) + m0 + 8] = __float2half_rn(c[nt][3]);
    }
}

__device__ __forceinline__ void eval_fh(
    const unsigned (&A1)[4][4], const unsigned (&A2)[4][4],
    float b1lo, float b1hi, float b2lo, float b2hi,
    const unsigned* __restrict__ sY, unsigned* __restrict__ sH,
    int m0, int g, int tig, float (&k)[2][4])
{
    float h[2][4];
    gemm16h(A1, sY, b1lo, b1hi, g, tig, h);
#pragma unroll
    for (int nt = 0; nt < 2; nt++)
#pragma unroll
        for (int e = 0; e < 4; e++) h[nt][e] = tanhap(h[nt][e]);
    store_frag_h(sH, h, m0, tig);
    __syncthreads();
    gemm16h(A2, sH, b2lo, b2hi, g, tig, k);
}

__global__ void __launch_bounds__(128, 4) ode_kernel(
    const float* __restrict__ t_span,
    const float* __restrict__ w1g, const float* __restrict__ b1g,
    const float* __restrict__ w2g, const float* __restrict__ b2g,
    const float* __restrict__ r1w, const float* __restrict__ r1b,
    const float* __restrict__ r2w, const float* __restrict__ r2b,
    float* __restrict__ out, int B)
{
    __shared__ unsigned sODE[2 * ODE_SPB * KW];
    unsigned* sY = sODE;
    unsigned* sH = sODE + ODE_SPB * KW;

    const int tid  = threadIdx.x;
    const int w    = tid >> 5;
    const int lane = tid & 31;
    const int g    = lane >> 2;
    const int tig  = lane & 3;
    const int m0   = w * 16 + g;

    unsigned A1[4][4], A2[4][4];
#pragma unroll
    for (int kt = 0; kt < 4; kt++) {
        const int k0 = kt * 16 + 2 * tig;
        A1[kt][0] = pkh2(__ldg(&w1g[(m0)     * HID + k0]),     __ldg(&w1g[(m0)     * HID + k0 + 1]));
        A1[kt][1] = pkh2(__ldg(&w1g[(m0 + 8) * HID + k0]),     __ldg(&w1g[(m0 + 8) * HID + k0 + 1]));
        A1[kt][2] = pkh2(__ldg(&w1g[(m0)     * HID + k0 + 8]), __ldg(&w1g[(m0)     * HID + k0 + 9]));
        A1[kt][3] = pkh2(__ldg(&w1g[(m0 + 8) * HID + k0 + 8]), __ldg(&w1g[(m0 + 8) * HID + k0 + 9]));
        A2[kt][0] = pkh2(__ldg(&w2g[(m0)     * HID + k0]),     __ldg(&w2g[(m0)     * HID + k0 + 1]));
        A2[kt][1] = pkh2(__ldg(&w2g[(m0 + 8) * HID + k0]),     __ldg(&w2g[(m0 + 8) * HID + k0 + 1]));
        A2[kt][2] = pkh2(__ldg(&w2g[(m0)     * HID + k0 + 8]), __ldg(&w2g[(m0)     * HID + k0 + 9]));
        A2[kt][3] = pkh2(__ldg(&w2g[(m0 + 8) * HID + k0 + 8]), __ldg(&w2g[(m0 + 8) * HID + k0 + 9]));
    }
    const float b1lo = __ldg(&b1g[m0]), b1hi = __ldg(&b1g[m0 + 8]);
    const float b2lo = __ldg(&b2g[m0]), b2hi = __ldg(&b2g[m0 + 8]);

    const float dt = (__ldg(&t_span[1]) - __ldg(&t_span[0])) * (1.0f / STEPS);

    const long long gbase = (long long)blockIdx.x * ODE_SPB;
    float y[2][4];
#pragma unroll
    for (int nt = 0; nt < 2; nt++) {
        const long long n0 = gbase + nt * 8 + 2 * tig;
        y[nt][0] = __ldg(&g_theta0[(size_t)m0 * B + n0]);
        y[nt][1] = __ldg(&g_theta0[(size_t)m0 * B + n0 + 1]);
        y[nt][2] = __ldg(&g_theta0[(size_t)(m0 + 8) * B + n0]);
        y[nt][3] = __ldg(&g_theta0[(size_t)(m0 + 8) * B + n0 + 1]);
    }
    store_frag_h(sY, y, m0, tig);
    __syncthreads();

    float k1[2][4], k2[2][4], k3[2][4], k4[2][4], k5[2][4], k6[2][4], nv[2][4];

#define ELEM_LOOP(expr)                                                        \
    _Pragma("unroll") for (int nt = 0; nt < 2; nt++)                           \
    _Pragma("unroll") for (int e = 0; e < 4; e++) { expr; }

    for (int step = 0; step < STEPS; step++) {
        eval_fh(A1, A2, b1lo, b1hi, b2lo, b2hi, sY, sH, m0, g, tig, k1);
        {
            const float c1 = dt * 0.2f;
            ELEM_LOOP(nv[nt][e] = fmaf(c1, k1[nt][e], y[nt][e]));
            store_frag_h(sY, nv, m0, tig);
        }
        __syncthreads();
        eval_fh(A1, A2, b1lo, b1hi, b2lo, b2hi, sY, sH, m0, g, tig, k2);
        {
            const float c1 = dt * (3.0f / 40.0f), c2 = dt * (9.0f / 40.0f);
            ELEM_LOOP(nv[nt][e] = fmaf(c1, k1[nt][e], fmaf(c2, k2[nt][e], y[nt][e])));
            store_frag_h(sY, nv, m0, tig);
        }
        __syncthreads();
        eval_fh(A1, A2, b1lo, b1hi, b2lo, b2hi, sY, sH, m0, g, tig, k3);
        {
            const float c1 = dt * (44.0f / 45.0f), c2 = dt * (-56.0f / 15.0f),
                        c3 = dt * (32.0f / 9.0f);
            ELEM_LOOP(nv[nt][e] = fmaf(c1, k1[nt][e], fmaf(c2, k2[nt][e],
                                  fmaf(c3, k3[nt][e], y[nt][e]))));
            store_frag_h(sY, nv, m0, tig);
        }
        __syncthreads();
        eval_fh(A1, A2, b1lo, b1hi, b2lo, b2hi, sY, sH, m0, g, tig, k4);
        {
            const float c1 = dt * (19372.0f / 6561.0f), c2 = dt * (-25360.0f / 2187.0f),
                        c3 = dt * (64448.0f / 6561.0f), c4 = dt * (-212.0f / 729.0f);
            ELEM_LOOP(nv[nt][e] = fmaf(c1, k1[nt][e], fmaf(c2, k2[nt][e],
                                  fmaf(c3, k3[nt][e], fmaf(c4, k4[nt][e], y[nt][e])))));
            store_frag_h(sY, nv, m0, tig);
        }
        __syncthreads();
        eval_fh(A1, A2, b1lo, b1hi, b2lo, b2hi, sY, sH, m0, g, tig, k5);
        {
            const float c1 = dt * (9017.0f / 3168.0f), c2 = dt * (-355.0f / 33.0f),
                        c3 = dt * (46732.0f / 5247.0f), c4 = dt * (49.0f / 176.0f),
                        c5 = dt * (-5103.0f / 18656.0f);
            ELEM_LOOP(nv[nt][e] = fmaf(c1, k1[nt][e], fmaf(c2, k2[nt][e],
                                  fmaf(c3, k3[nt][e], fmaf(c4, k4[nt][e],
                                  fmaf(c5, k5[nt][e], y[nt][e]))))));
            store_frag_h(sY, nv, m0, tig);
        }
        __syncthreads();
        eval_fh(A1, A2, b1lo, b1hi, b2lo, b2hi, sY, sH, m0, g, tig, k6);
        {
            const float c1 = dt * (35.0f / 384.0f),  c3 = dt * (500.0f / 1113.0f),
                        c4 = dt * (125.0f / 192.0f), c5 = dt * (-2187.0f / 6784.0f),
                        c6 = dt * (11.0f / 84.0f);
            ELEM_LOOP(y[nt][e] = fmaf(c1, k1[nt][e], fmaf(c3, k3[nt][e],
                                 fmaf(c4, k4[nt][e], fmaf(c5, k5[nt][e],
                                 fmaf(c6, k6[nt][e], y[nt][e]))))));
            store_frag_h(sY, y, m0, tig);
        }
        __syncthreads();
    }

    {
        float* sYf = (float*)sODE;
#pragma unroll
        for (int nt = 0; nt < 2; nt++) {
            const int n0 = nt * 8 + 2 * tig;
            sYf[(n0)     * 68 + m0]     = y[nt][0];
            sYf[(n0 + 1) * 68 + m0]     = y[nt][1];
            sYf[(n0)     * 68 + m0 + 8] = y[nt][2];
            sYf[(n0 + 1) * 68 + m0 + 8] = y[nt][3];
        }
    }
    __syncthreads();

    {
        const float* sYf = (const float*)sODE;
        const int s  = tid >> 3;
        const int mg = (tid & 7) * 4;
        float accm[4];
#pragma unroll
        for (int m = 0; m < 4; m++) accm[m] = __ldg(&r1b[mg + m]);
        for (int i = 0; i < HID; i++) {
            const float yy = sYf[s * 68 + i];
#pragma unroll
            for (int m = 0; m < 4; m++)
                accm[m] = fmaf(__ldg(&r1w[(mg + m) * HID + i]), yy, accm[m]);
        }
        float part = 0.0f;
#pragma unroll
        for (int m = 0; m < 4; m++)
            part = fmaf(__ldg(&r2w[mg + m]), fmaxf(accm[m], 0.0f), part);
        part += __shfl_xor_sync(0xffffffffu, part, 1);
        part += __shfl_xor_sync(0xffffffffu, part, 2);
        part += __shfl_xor_sync(0xffffffffu, part, 4);
        if ((tid & 7) == 0)
            out[(long long)blockIdx.x * ODE_SPB + s] = part + __ldg(&r2b[0]);
    }
}

// ============================== launch ======================================
extern "C" void kernel_launch(void* const* d_in, const int* in_sizes, int n_in,
                              void* d_out, int out_size)
{
    const float* x      = (const float*)d_in[0];
    const float* t_span = (const float*)d_in[1];
    const float* conv_w = (const float*)d_in[2];
    const float* conv_b = (const float*)d_in[3];
    const float* enc1_w = (const float*)d_in[4];
    const float* enc1_b = (const float*)d_in[5];
    const float* enc2_w = (const float*)d_in[6];
    const float* enc2_b = (const float*)d_in[7];
    const float* ode1_w = (const float*)d_in[8];
    const float* ode1_b = (const float*)d_in[9];
    const float* ode2_w = (const float*)d_in[10];
    const float* ode2_b = (const float*)d_in[11];
    const float* reg1_w = (const float*)d_in[12];
    const float* reg1_b = (const float*)d_in[13];
    const float* reg2_w = (const float*)d_in[14];
    const float* reg2_b = (const float*)d_in[15];
    float* out = (float*)d_out;

    const int B = in_sizes[0] / (SEQ * INC);

    cudaFuncSetAttribute(enc_kernel, cudaFuncAttributeMaxDynamicSharedMemorySize,
                         ENC_SMEM_BYTES);

    enc_kernel<<<B / ENC_SPB, 256, ENC_SMEM_BYTES>>>(
        x, conv_w, conv_b, enc1_w, enc1_b, enc2_w, enc2_b, B);
    ode_kernel<<<B / ODE_SPB, 128>>>(
        t_span, ode1_w, ode1_b, ode2_w, ode2_b,
        reg1_w, reg1_b, reg2_w, reg2_b, out, B);
}

// round 16
// speedup vs baseline: 1.6752x; 1.6752x over previous
#include <cuda_runtime.h>
#include <cuda_bf16.h>
#include <cuda_fp16.h>

// ---------------------------------------------------------------------------
// CNN_ODE: conv1d+SiLU (R14 conv, fp32 intermediate) -> in-place fp16 repack
// -> enc1 fp16 mma (double-buffered) -> enc2 -> 50-step dopri5 (fp16 mma ODE,
// 16-sample CTAs) -> regressor.  B = 65536.
// ---------------------------------------------------------------------------

#define SEQ   40
#define INC   24
#define NK    36
#define FLAT  1440
#define HID   64
#define STEPS 50

__device__ float g_theta0[HID * 65536];   // [dim][sample], fp32

__device__ __forceinline__ float tanhap(float x) {
    float r; asm("tanh.approx.f32 %0,%1;" : "=f"(r) : "f"(x)); return r;
}
__device__ __forceinline__ void mma_fp16(
    float (&c)[4], const unsigned (&a)[4], unsigned b0, unsigned b1)
{
    asm("mma.sync.aligned.m16n8k16.row.col.f32.f16.f16.f32 "
        "{%0,%1,%2,%3},{%4,%5,%6,%7},{%8,%9},{%0,%1,%2,%3};"
        : "+f"(c[0]), "+f"(c[1]), "+f"(c[2]), "+f"(c[3])
        : "r"(a[0]), "r"(a[1]), "r"(a[2]), "r"(a[3]), "r"(b0), "r"(b1));
}
__device__ __forceinline__ unsigned pkh2(float a, float b) {
    __half2 h = __floats2half2_rn(a, b);
    return *reinterpret_cast<unsigned*>(&h);
}

// ============================== Encoder ====================================
// 32 samples/CTA, 256 threads.
//  conv (R14): fp32 intermediate sC32 [32][1444]
//  repack: in-place -> fp16 sC16 [32][724 words]
//  enc1: fp16 mma, double-buffered weight chunks [128][20 words] x2
#define ENC_SPB 32
#define SCST    1444                   // fp32 conv row stride (floats)
#define SCW     724                    // fp16 row stride (words); 724%32==20
#define SWW     20                     // fp16 weight chunk row stride (words)
#define SH1ST   132
#define NCHUNK  (FLAT / 32)            // 45
#define ENC_SMEM_WORDS (ENC_SPB * SCST + 2 * 128 * SWW)   // 51328
#define ENC_SMEM_BYTES (ENC_SMEM_WORDS * 4)               // 205312

__global__ void __launch_bounds__(256) enc_kernel(
    const float* __restrict__ x,
    const float* __restrict__ conv_w, const float* __restrict__ conv_b,
    const float* __restrict__ enc1_w, const float* __restrict__ enc1_b,
    const float* __restrict__ enc2_w, const float* __restrict__ enc2_b,
    int B)
{
    extern __shared__ unsigned smu[];
    unsigned* sC  = smu;                          // fp32 conv out / fp16 after repack
    unsigned* sW0 = sC + ENC_SPB * SCST;          // fp16 weight buf 0 (2560 w)
    unsigned* sW1 = sW0 + 128 * SWW;              // fp16 weight buf 1 (2560 w)
    float*    sH1 = (float*)sC;                   // [32][132] (aliases sC)
    float*    scw = (float*)sW0;                  // conv weights (2592 f, spans sW0+sW1)

    const int tid = threadIdx.x;
    const long long blk = blockIdx.x;

    for (int i = tid; i < NK * 72; i += 256) scw[i] = conv_w[i];
    __syncthreads();

    // ---- conv1d (pad=1) + SiLU, R14 structure: x read once per c-half ----
    {
        const int sp = tid >> 3;
        const int sq = tid & 7;
        const float* xs = x + (blk * ENC_SPB + sp) * (SEQ * INC);
        float* sCf = (float*)sC;
#pragma unroll
        for (int ch = 0; ch < 2; ch++) {
            const int c0 = ch * 12;
            float xr[7][12];
#pragma unroll
            for (int r = 0; r < 7; r++) {
                const int s = sq * 5 - 1 + r;
                if (s >= 0 && s < SEQ) {
                    const float4 v0 = __ldg((const float4*)(xs + s * INC + c0));
                    const float4 v1 = __ldg((const float4*)(xs + s * INC + c0 + 4));
                    const float4 v2 = __ldg((const float4*)(xs + s * INC + c0 + 8));
                    xr[r][0]=v0.x; xr[r][1]=v0.y; xr[r][2]=v0.z; xr[r][3]=v0.w;
                    xr[r][4]=v1.x; xr[r][5]=v1.y; xr[r][6]=v1.z; xr[r][7]=v1.w;
                    xr[r][8]=v2.x; xr[r][9]=v2.y; xr[r][10]=v2.z; xr[r][11]=v2.w;
                } else {
#pragma unroll
                    for (int cc = 0; cc < 12; cc++) xr[r][cc] = 0.0f;
                }
            }
            for (int k = 0; k < NK; k++) {
                float acc[5];
                if (ch == 0) {
                    const float bk = __ldg(&conv_b[k]);
#pragma unroll
                    for (int i = 0; i < 5; i++) acc[i] = bk;
                } else {
#pragma unroll
                    for (int i = 0; i < 5; i++)
                        acc[i] = sCf[sp * SCST + k * SEQ + sq * 5 + i];
                }
#pragma unroll
                for (int cc = 0; cc < 12; cc++) {
                    const float w0 = scw[k * 72 + (c0 + cc) * 3 + 0];
                    const float w1 = scw[k * 72 + (c0 + cc) * 3 + 1];
                    const float w2 = scw[k * 72 + (c0 + cc) * 3 + 2];
#pragma unroll
                    for (int i = 0; i < 5; i++) {
                        acc[i] = fmaf(w0, xr[i][cc],     acc[i]);
                        acc[i] = fmaf(w1, xr[i + 1][cc], acc[i]);
                        acc[i] = fmaf(w2, xr[i + 2][cc], acc[i]);
                    }
                }
                if (ch == 0) {
#pragma unroll
                    for (int i = 0; i < 5; i++)
                        sCf[sp * SCST + k * SEQ + sq * 5 + i] = acc[i];
                } else {
#pragma unroll
                    for (int i = 0; i < 5; i++) {
                        const float v  = acc[i];
                        const float sg = fmaf(0.5f, tanhap(0.5f * v), 0.5f);
                        sCf[sp * SCST + k * SEQ + sq * 5 + i] = v * sg;   // fp32
                    }
                }
            }
        }
    }
    __syncthreads();

    // ---- in-place repack fp32 [32][1444] -> fp16 words [32][724] ----
    // iter sp: reads fp32 [1444sp, 1444sp+1440), writes [724sp, 724sp+720).
    // Disjoint for sp>=1; cross-iteration disjoint (proof in header comment).
    {
        const float* sCf = (const float*)sC;
        {   // sp = 0: read-to-regs, barrier, write
            float2 v[3];
#pragma unroll
            for (int j = 0; j < 3; j++) {
                const int t = tid + j * 256;
                if (t < 720) v[j] = *(const float2*)(sCf + 2 * t);
            }
            __syncthreads();
#pragma unroll
            for (int j = 0; j < 3; j++) {
                const int t = tid + j * 256;
                if (t < 720) sC[t] = pkh2(v[j].x, v[j].y);
            }
        }
        for (int sp = 1; sp < ENC_SPB; sp++) {
#pragma unroll
            for (int j = 0; j < 3; j++) {
                const int t = tid + j * 256;
                if (t < 720) {
                    const float2 vv = *(const float2*)(sCf + sp * SCST + 2 * t);
                    sC[sp * SCW + t] = pkh2(vv.x, vv.y);
                }
            }
        }
    }
    __syncthreads();

    // ---- enc1 via fp16 mma: C[32 samp][128 out], K=1440, double-buffered ----
    const int w    = tid >> 5;
    const int lane = tid & 31;
    const int g    = lane >> 2;
    const int tig  = lane & 3;
    const int mh   = w & 1;
    const int nq   = w >> 1;
    const int srow = mh * 16 + g;
    const int nbase = nq * 32;

    float c[4][4];
#pragma unroll
    for (int nt = 0; nt < 4; nt++) {
        const int n0 = nbase + nt * 8 + 2 * tig;
        c[nt][0] = __ldg(&enc1_b[n0]);
        c[nt][1] = __ldg(&enc1_b[n0 + 1]);
        c[nt][2] = c[nt][0];
        c[nt][3] = c[nt][1];
    }

    float4 pre[4];
#pragma unroll
    for (int j = 0; j < 4; j++) {
        const int f  = tid + j * 256;
        const int oc = f >> 3, qd = f & 7;
        pre[j] = __ldg((const float4*)(enc1_w + (size_t)oc * FLAT + qd * 4));
    }

    for (int kci = 0; kci < NCHUNK; kci++) {
        unsigned* buf = (kci & 1) ? sW1 : sW0;
#pragma unroll
        for (int j = 0; j < 4; j++) {
            const int f  = tid + j * 256;
            const int oc = f >> 3, qd = f & 7;
            uint2 u;
            u.x = pkh2(pre[j].x, pre[j].y);
            u.y = pkh2(pre[j].z, pre[j].w);
            *(uint2*)(buf + oc * SWW + qd * 2) = u;
        }
        if (kci + 1 < NCHUNK) {
            const int kc = (kci + 1) * 32;
#pragma unroll
            for (int j = 0; j < 4; j++) {
                const int f  = tid + j * 256;
                const int oc = f >> 3, qd = f & 7;
                pre[j] = __ldg((const float4*)(enc1_w + (size_t)oc * FLAT + kc + qd * 4));
            }
        }
        __syncthreads();
        const int kw = kci * 16;               // chunk base in fp16 words
#pragma unroll
        for (int kt = 0; kt < 2; kt++) {
            unsigned a[4];
            const unsigned* ar = sC + srow * SCW + kw + kt * 8 + tig;
            a[0] = ar[0];
            a[1] = ar[8 * SCW];
            a[2] = ar[4];
            a[3] = ar[8 * SCW + 4];
#pragma unroll
            for (int nt = 0; nt < 4; nt++) {
                const unsigned* br = buf + (nbase + nt * 8 + g) * SWW + kt * 8 + tig;
                mma_fp16(c[nt], a, br[0], br[4]);
            }
        }
    }
    __syncthreads();   // all mma reads of sC done -> sH1 may overwrite it

#pragma unroll
    for (int nt = 0; nt < 4; nt++) {
        const int n0 = nbase + nt * 8 + 2 * tig;
        sH1[srow * SH1ST + n0]           = fmaxf(c[nt][0], 0.0f);
        sH1[srow * SH1ST + n0 + 1]       = fmaxf(c[nt][1], 0.0f);
        sH1[(srow + 8) * SH1ST + n0]     = fmaxf(c[nt][2], 0.0f);
        sH1[(srow + 8) * SH1ST + n0 + 1] = fmaxf(c[nt][3], 0.0f);
    }
    __syncthreads();

    // ---- enc2: [128 -> 64] -> g_theta0 transposed [dim][sample] ----
    for (int t = tid; t < ENC_SPB * HID; t += 256) {
        const int oc = t >> 5;
        const int sp = t & 31;
        float acc = __ldg(&enc2_b[oc]);
        const float* wr = enc2_w + oc * 128;
        const float* hv = sH1 + sp * SH1ST;
#pragma unroll
        for (int i = 0; i < 128; i += 4) {
            const float4 wv = __ldg((const float4*)(wr + i));
            const float4 h4 = *(const float4*)(hv + i);
            acc = fmaf(wv.x, h4.x, fmaf(wv.y, h4.y, fmaf(wv.z, h4.z, fmaf(wv.w, h4.w, acc))));
        }
        g_theta0[(size_t)oc * B + blk * ENC_SPB + sp] = acc;
    }
}

// ================================ ODE (unchanged R14) =======================
#define ODE_SPB 16
#define KW 36

__device__ __forceinline__ void gemm16h(
    const unsigned (&A)[4][4], const unsigned* __restrict__ sIn,
    float blo, float bhi, int g, int tig, float (&c)[2][4])
{
#pragma unroll
    for (int nt = 0; nt < 2; nt++) {
        c[nt][0] = blo; c[nt][1] = blo; c[nt][2] = bhi; c[nt][3] = bhi;
    }
#pragma unroll
    for (int kt = 0; kt < 4; kt++) {
#pragma unroll
        for (int nt = 0; nt < 2; nt++) {
            const unsigned* r = sIn + (nt * 8 + g) * KW + kt * 8 + tig;
            mma_fp16(c[nt], A[kt], r[0], r[4]);
        }
    }
}

__device__ __forceinline__ void store_frag_h(
    unsigned* __restrict__ dst, const float (&c)[2][4], int m0, int tig)
{
    __half* d = (__half*)dst;
#pragma unroll
    for (int nt = 0; nt < 2; nt++) {
        const int n0 = nt * 8 + 2 * tig;
        d[(n0)     * (2*KW) + m0]     = __float2half_rn(c[nt][0]);
        d[(n0 + 1) * (2*KW) + m0]     = __float2half_rn(c[nt][1]);
        d[(n0)     * (2*KW) + m0 + 8] = __float2half_rn(c[nt][2]);
        d[(n0 + 1) * (2*KW) + m0 + 8] = __float2half_rn(c[nt][3]);
    }
}

__device__ __forceinline__ void eval_fh(
    const unsigned (&A1)[4][4], const unsigned (&A2)[4][4],
    float b1lo, float b1hi, float b2lo, float b2hi,
    const unsigned* __restrict__ sY, unsigned* __restrict__ sH,
    int m0, int g, int tig, float (&k)[2][4])
{
    float h[2][4];
    gemm16h(A1, sY, b1lo, b1hi, g, tig, h);
#pragma unroll
    for (int nt = 0; nt < 2; nt++)
#pragma unroll
        for (int e = 0; e < 4; e++) h[nt][e] = tanhap(h[nt][e]);
    store_frag_h(sH, h, m0, tig);
    __syncthreads();
    gemm16h(A2, sH, b2lo, b2hi, g, tig, k);
}

__global__ void __launch_bounds__(128, 4) ode_kernel(
    const float* __restrict__ t_span,
    const float* __restrict__ w1g, const float* __restrict__ b1g,
    const float* __restrict__ w2g, const float* __restrict__ b2g,
    const float* __restrict__ r1w, const float* __restrict__ r1b,
    const float* __restrict__ r2w, const float* __restrict__ r2b,
    float* __restrict__ out, int B)
{
    __shared__ unsigned sODE[2 * ODE_SPB * KW];
    unsigned* sY = sODE;
    unsigned* sH = sODE + ODE_SPB * KW;

    const int tid  = threadIdx.x;
    const int w    = tid >> 5;
    const int lane = tid & 31;
    const int g    = lane >> 2;
    const int tig  = lane & 3;
    const int m0   = w * 16 + g;

    unsigned A1[4][4], A2[4][4];
#pragma unroll
    for (int kt = 0; kt < 4; kt++) {
        const int k0 = kt * 16 + 2 * tig;
        A1[kt][0] = pkh2(__ldg(&w1g[(m0)     * HID + k0]),     __ldg(&w1g[(m0)     * HID + k0 + 1]));
        A1[kt][1] = pkh2(__ldg(&w1g[(m0 + 8) * HID + k0]),     __ldg(&w1g[(m0 + 8) * HID + k0 + 1]));
        A1[kt][2] = pkh2(__ldg(&w1g[(m0)     * HID + k0 + 8]), __ldg(&w1g[(m0)     * HID + k0 + 9]));
        A1[kt][3] = pkh2(__ldg(&w1g[(m0 + 8) * HID + k0 + 8]), __ldg(&w1g[(m0 + 8) * HID + k0 + 9]));
        A2[kt][0] = pkh2(__ldg(&w2g[(m0)     * HID + k0]),     __ldg(&w2g[(m0)     * HID + k0 + 1]));
        A2[kt][1] = pkh2(__ldg(&w2g[(m0 + 8) * HID + k0]),     __ldg(&w2g[(m0 + 8) * HID + k0 + 1]));
        A2[kt][2] = pkh2(__ldg(&w2g[(m0)     * HID + k0 + 8]), __ldg(&w2g[(m0)     * HID + k0 + 9]));
        A2[kt][3] = pkh2(__ldg(&w2g[(m0 + 8) * HID + k0 + 8]), __ldg(&w2g[(m0 + 8) * HID + k0 + 9]));
    }
    const float b1lo = __ldg(&b1g[m0]), b1hi = __ldg(&b1g[m0 + 8]);
    const float b2lo = __ldg(&b2g[m0]), b2hi = __ldg(&b2g[m0 + 8]);

    const float dt = (__ldg(&t_span[1]) - __ldg(&t_span[0])) * (1.0f / STEPS);

    const long long gbase = (long long)blockIdx.x * ODE_SPB;
    float y[2][4];
#pragma unroll
    for (int nt = 0; nt < 2; nt++) {
        const long long n0 = gbase + nt * 8 + 2 * tig;
        y[nt][0] = __ldg(&g_theta0[(size_t)m0 * B + n0]);
        y[nt][1] = __ldg(&g_theta0[(size_t)m0 * B + n0 + 1]);
        y[nt][2] = __ldg(&g_theta0[(size_t)(m0 + 8) * B + n0]);
        y[nt][3] = __ldg(&g_theta0[(size_t)(m0 + 8) * B + n0 + 1]);
    }
    store_frag_h(sY, y, m0, tig);
    __syncthreads();

    float k1[2][4], k2[2][4], k3[2][4], k4[2][4], k5[2][4], k6[2][4], nv[2][4];

#define ELEM_LOOP(expr)                                                        \
    _Pragma("unroll") for (int nt = 0; nt < 2; nt++)                           \
    _Pragma("unroll") for (int e = 0; e < 4; e++) { expr; }

    for (int step = 0; step < STEPS; step++) {
        eval_fh(A1, A2, b1lo, b1hi, b2lo, b2hi, sY, sH, m0, g, tig, k1);
        {
            const float c1 = dt * 0.2f;
            ELEM_LOOP(nv[nt][e] = fmaf(c1, k1[nt][e], y[nt][e]));
            store_frag_h(sY, nv, m0, tig);
        }
        __syncthreads();
        eval_fh(A1, A2, b1lo, b1hi, b2lo, b2hi, sY, sH, m0, g, tig, k2);
        {
            const float c1 = dt * (3.0f / 40.0f), c2 = dt * (9.0f / 40.0f);
            ELEM_LOOP(nv[nt][e] = fmaf(c1, k1[nt][e], fmaf(c2, k2[nt][e], y[nt][e])));
            store_frag_h(sY, nv, m0, tig);
        }
        __syncthreads();
        eval_fh(A1, A2, b1lo, b1hi, b2lo, b2hi, sY, sH, m0, g, tig, k3);
        {
            const float c1 = dt * (44.0f / 45.0f), c2 = dt * (-56.0f / 15.0f),
                        c3 = dt * (32.0f / 9.0f);
            ELEM_LOOP(nv[nt][e] = fmaf(c1, k1[nt][e], fmaf(c2, k2[nt][e],
                                  fmaf(c3, k3[nt][e], y[nt][e]))));
            store_frag_h(sY, nv, m0, tig);
        }
        __syncthreads();
        eval_fh(A1, A2, b1lo, b1hi, b2lo, b2hi, sY, sH, m0, g, tig, k4);
        {
            const float c1 = dt * (19372.0f / 6561.0f), c2 = dt * (-25360.0f / 2187.0f),
                        c3 = dt * (64448.0f / 6561.0f), c4 = dt * (-212.0f / 729.0f);
            ELEM_LOOP(nv[nt][e] = fmaf(c1, k1[nt][e], fmaf(c2, k2[nt][e],
                                  fmaf(c3, k3[nt][e], fmaf(c4, k4[nt][e], y[nt][e])))));
            store_frag_h(sY, nv, m0, tig);
        }
        __syncthreads();
        eval_fh(A1, A2, b1lo, b1hi, b2lo, b2hi, sY, sH, m0, g, tig, k5);
        {
            const float c1 = dt * (9017.0f / 3168.0f), c2 = dt * (-355.0f / 33.0f),
                        c3 = dt * (46732.0f / 5247.0f), c4 = dt * (49.0f / 176.0f),
                        c5 = dt * (-5103.0f / 18656.0f);
            ELEM_LOOP(nv[nt][e] = fmaf(c1, k1[nt][e], fmaf(c2, k2[nt][e],
                                  fmaf(c3, k3[nt][e], fmaf(c4, k4[nt][e],
                                  fmaf(c5, k5[nt][e], y[nt][e]))))));
            store_frag_h(sY, nv, m0, tig);
        }
        __syncthreads();
        eval_fh(A1, A2, b1lo, b1hi, b2lo, b2hi, sY, sH, m0, g, tig, k6);
        {
            const float c1 = dt * (35.0f / 384.0f),  c3 = dt * (500.0f / 1113.0f),
                        c4 = dt * (125.0f / 192.0f), c5 = dt * (-2187.0f / 6784.0f),
                        c6 = dt * (11.0f / 84.0f);
            ELEM_LOOP(y[nt][e] = fmaf(c1, k1[nt][e], fmaf(c3, k3[nt][e],
                                 fmaf(c4, k4[nt][e], fmaf(c5, k5[nt][e],
                                 fmaf(c6, k6[nt][e], y[nt][e]))))));
            store_frag_h(sY, y, m0, tig);
        }
        __syncthreads();
    }

    {
        float* sYf = (float*)sODE;
#pragma unroll
        for (int nt = 0; nt < 2; nt++) {
            const int n0 = nt * 8 + 2 * tig;
            sYf[(n0)     * 68 + m0]     = y[nt][0];
            sYf[(n0 + 1) * 68 + m0]     = y[nt][1];
            sYf[(n0)     * 68 + m0 + 8] = y[nt][2];
            sYf[(n0 + 1) * 68 + m0 + 8] = y[nt][3];
        }
    }
    __syncthreads();

    {
        const float* sYf = (const float*)sODE;
        const int s  = tid >> 3;
        const int mg = (tid & 7) * 4;
        float accm[4];
#pragma unroll
        for (int m = 0; m < 4; m++) accm[m] = __ldg(&r1b[mg + m]);
        for (int i = 0; i < HID; i++) {
            const float yy = sYf[s * 68 + i];
#pragma unroll
            for (int m = 0; m < 4; m++)
                accm[m] = fmaf(__ldg(&r1w[(mg + m) * HID + i]), yy, accm[m]);
        }
        float part = 0.0f;
#pragma unroll
        for (int m = 0; m < 4; m++)
            part = fmaf(__ldg(&r2w[mg + m]), fmaxf(accm[m], 0.0f), part);
        part += __shfl_xor_sync(0xffffffffu, part, 1);
        part += __shfl_xor_sync(0xffffffffu, part, 2);
        part += __shfl_xor_sync(0xffffffffu, part, 4);
        if ((tid & 7) == 0)
            out[(long long)blockIdx.x * ODE_SPB + s] = part + __ldg(&r2b[0]);
    }
}

// ============================== launch ======================================
extern "C" void kernel_launch(void* const* d_in, const int* in_sizes, int n_in,
                              void* d_out, int out_size)
{
    const float* x      = (const float*)d_in[0];
    const float* t_span = (const float*)d_in[1];
    const float* conv_w = (const float*)d_in[2];
    const float* conv_b = (const float*)d_in[3];
    const float* enc1_w = (const float*)d_in[4];
    const float* enc1_b = (const float*)d_in[5];
    const float* enc2_w = (const float*)d_in[6];
    const float* enc2_b = (const float*)d_in[7];
    const float* ode1_w = (const float*)d_in[8];
    const float* ode1_b = (const float*)d_in[9];
    const float* ode2_w = (const float*)d_in[10];
    const float* ode2_b = (const float*)d_in[11];
    const float* reg1_w = (const float*)d_in[12];
    const float* reg1_b = (const float*)d_in[13];
    const float* reg2_w = (const float*)d_in[14];
    const float* reg2_b = (const float*)d_in[15];
    float* out = (float*)d_out;

    const int B = in_sizes[0] / (SEQ * INC);

    cudaFuncSetAttribute(enc_kernel, cudaFuncAttributeMaxDynamicSharedMemorySize,
                         ENC_SMEM_BYTES);

    enc_kernel<<<B / ENC_SPB, 256, ENC_SMEM_BYTES>>>(
        x, conv_w, conv_b, enc1_w, enc1_b, enc2_w, enc2_b, B);
    ode_kernel<<<B / ODE_SPB, 128>>>(
        t_span, ode1_w, ode1_b, ode2_w, ode2_b,
        reg1_w, reg1_b, reg2_w, reg2_b, out, B);
}

// round 17
// speedup vs baseline: 1.9113x; 1.1410x over previous
#include <cuda_runtime.h>
#include <cuda_bf16.h>
#include <cuda_fp16.h>

// ---------------------------------------------------------------------------
// CNN_ODE: conv1d as 3-shifted fp16 GEMM (tensor cores) + fused SiLU ->
// enc1 fp16 mma (double-buffered) -> enc2 -> 50-step dopri5 (fp16 mma ODE,
// 16-sample CTAs) -> regressor.  B = 65536.
// ---------------------------------------------------------------------------

#define SEQ   40
#define INC   24
#define NK    36
#define FLAT  1440
#define HID   64
#define STEPS 50

__device__ float g_theta0[HID * 65536];   // [dim][sample], fp32

__device__ __forceinline__ float tanhap(float x) {
    float r; asm("tanh.approx.f32 %0,%1;" : "=f"(r) : "f"(x)); return r;
}
__device__ __forceinline__ void mma_fp16(
    float (&c)[4], const unsigned (&a)[4], unsigned b0, unsigned b1)
{
    asm("mma.sync.aligned.m16n8k16.row.col.f32.f16.f16.f32 "
        "{%0,%1,%2,%3},{%4,%5,%6,%7},{%8,%9},{%0,%1,%2,%3};"
        : "+f"(c[0]), "+f"(c[1]), "+f"(c[2]), "+f"(c[3])
        : "r"(a[0]), "r"(a[1]), "r"(a[2]), "r"(a[3]), "r"(b0), "r"(b1));
}
__device__ __forceinline__ unsigned pkh2(float a, float b) {
    __half2 h = __floats2half2_rn(a, b);
    return *reinterpret_cast<unsigned*>(&h);
}
__device__ __forceinline__ float siluap(float v) {
    return v * fmaf(0.5f, tanhap(0.5f * v), 0.5f);
}

// ============================== Encoder ====================================
// 32 samples/CTA, 256 threads.
//  X tile: fp16, physical rows 0..1345 (zero pads between samples), stride 18w
//  conv: 3-shift fp16 mma, W_j as B-frags in regs; SiLU+store -> sC fp16
//  enc1: fp16 mma, double-buffered weight chunks (alias X region)
#define ENC_SPB 32
#define SCW     724                    // sC row stride (words)
#define SWW     20                     // enc1 weight chunk row stride (words)
#define SH1ST   132
#define NCHUNK  (FLAT / 32)            // 45
#define XST     18                     // X row stride (words)
#define XROWS   1346
#define SC_WORDS (ENC_SPB * SCW)               // 23168
#define X_WORDS  (XROWS * XST)                 // 24228
#define ENC_SMEM_BYTES ((SC_WORDS + X_WORDS) * 4)   // 189584

__global__ void __launch_bounds__(256) enc_kernel(
    const float* __restrict__ x,
    const float* __restrict__ conv_w, const float* __restrict__ conv_b,
    const float* __restrict__ enc1_w, const float* __restrict__ enc1_b,
    const float* __restrict__ enc2_w, const float* __restrict__ enc2_b,
    int B)
{
    extern __shared__ unsigned smu[];
    unsigned* sC  = smu;                          // fp16 conv output
    unsigned* sX  = smu + SC_WORDS;               // fp16 padded x tile
    unsigned* sW0 = sX;                           // enc1 weight buf 0 (alias)
    unsigned* sW1 = sX + 128 * SWW;               // enc1 weight buf 1 (alias)
    float*    sH1 = (float*)sC;                   // [32][132] (aliases sC)

    const int tid  = threadIdx.x;
    const long long blk = blockIdx.x;
    const int w    = tid >> 5;
    const int lane = tid & 31;
    const int g    = lane >> 2;
    const int tig  = lane & 3;

    // ---- conv weights as fp16 B-fragments in registers ----
    // Bw[j][kt][nt]: n = nt*8+g (output kernel), k halves = kt*16+2tig(+8)
    unsigned Bw[3][2][5][2];
    float bs[5][2];
#pragma unroll
    for (int nt = 0; nt < 5; nt++) {
        const int nb = nt * 8 + 2 * tig;
        bs[nt][0] = (nb     < NK) ? __ldg(&conv_b[nb])     : 0.0f;
        bs[nt][1] = (nb + 1 < NK) ? __ldg(&conv_b[nb + 1]) : 0.0f;
        const int n = nt * 8 + g;
#pragma unroll
        for (int j = 0; j < 3; j++)
#pragma unroll
            for (int kt = 0; kt < 2; kt++) {
                const int cb = kt * 16 + 2 * tig;
                float f0 = 0.f, f1 = 0.f, f2 = 0.f, f3 = 0.f;
                if (n < NK) {
                    f0 = __ldg(&conv_w[n * 72 + cb * 3 + j]);
                    f1 = __ldg(&conv_w[n * 72 + (cb + 1) * 3 + j]);
                    if (cb + 8 < INC) {
                        f2 = __ldg(&conv_w[n * 72 + (cb + 8) * 3 + j]);
                        f3 = __ldg(&conv_w[n * 72 + (cb + 9) * 3 + j]);
                    }
                }
                Bw[j][kt][nt][0] = pkh2(f0, f1);
                Bw[j][kt][nt][1] = pkh2(f2, f3);
            }
    }

    // ---- stage X: zero-fill, then pack x fp32 -> fp16 at padded rows ----
    {
        uint4 z; z.x = z.y = z.z = z.w = 0u;
        for (int t = tid; t < X_WORDS / 4; t += 256)
            ((uint4*)sX)[t] = z;
    }
    __syncthreads();
    {
        const float* xg = x + blk * ENC_SPB * (SEQ * INC);
        for (int t = tid; t < ENC_SPB * SEQ * 12; t += 256) {
            const int i   = t / 480;
            const int rem = t - i * 480;
            const int s   = rem / 12;
            const int wd  = rem - s * 12;
            const float2 v = __ldg((const float2*)(xg + i * 960 + s * 24 + wd * 2));
            sX[(42 * i + 2 + s) * XST + wd] = pkh2(v.x, v.y);
        }
    }
    __syncthreads();

    // ---- conv as 3-shift mma over 84 m-tiles of 16 padded rows ----
    for (int mt = w; mt < 84; mt += 8) {
        float c[5][4];
#pragma unroll
        for (int nt = 0; nt < 5; nt++) {
            c[nt][0] = bs[nt][0]; c[nt][1] = bs[nt][1];
            c[nt][2] = bs[nt][0]; c[nt][3] = bs[nt][1];
        }
#pragma unroll
        for (int j = 0; j < 3; j++)
#pragma unroll
            for (int kt = 0; kt < 2; kt++) {
                unsigned a[4];
                const unsigned* ar = sX + (mt * 16 + j + g) * XST + kt * 8 + tig;
                a[0] = ar[0];
                a[1] = ar[8 * XST];
                a[2] = ar[4];
                a[3] = ar[8 * XST + 4];
#pragma unroll
                for (int nt = 0; nt < 5; nt++)
                    mma_fp16(c[nt], a, Bw[j][kt][nt][0], Bw[j][kt][nt][1]);
            }
        // SiLU + predicated store into sC fp16 [sample][k*40+s]
        const int p0 = mt * 16 + g, p1 = p0 + 8;
        const int i0 = p0 / 42, r0 = p0 - i0 * 42;
        const int i1 = p1 / 42, r1 = p1 - i1 * 42;
        const bool v0 = (r0 >= 1 && r0 <= 40);
        const bool v1 = (r1 >= 1 && r1 <= 40);
        __half* d = (__half*)sC;
#pragma unroll
        for (int nt = 0; nt < 5; nt++) {
            const int n0 = nt * 8 + 2 * tig;
            const float e0 = siluap(c[nt][0]);
            const float e1 = siluap(c[nt][1]);
            const float e2 = siluap(c[nt][2]);
            const float e3 = siluap(c[nt][3]);
            if (v0 && n0     < NK) d[i0 * 1448 + n0 * 40 + (r0 - 1)]       = __float2half_rn(e0);
            if (v0 && n0 + 1 < NK) d[i0 * 1448 + (n0 + 1) * 40 + (r0 - 1)] = __float2half_rn(e1);
            if (v1 && n0     < NK) d[i1 * 1448 + n0 * 40 + (r1 - 1)]       = __float2half_rn(e2);
            if (v1 && n0 + 1 < NK) d[i1 * 1448 + (n0 + 1) * 40 + (r1 - 1)] = __float2half_rn(e3);
        }
    }
    __syncthreads();   // conv done; sX region free for enc1 weight buffers

    // ---- enc1 via fp16 mma: C[32 samp][128 out], K=1440, double-buffered ----
    const int mh   = w & 1;
    const int nq   = w >> 1;
    const int srow = mh * 16 + g;
    const int nbase = nq * 32;

    float c[4][4];
#pragma unroll
    for (int nt = 0; nt < 4; nt++) {
        const int n0 = nbase + nt * 8 + 2 * tig;
        c[nt][0] = __ldg(&enc1_b[n0]);
        c[nt][1] = __ldg(&enc1_b[n0 + 1]);
        c[nt][2] = c[nt][0];
        c[nt][3] = c[nt][1];
    }

    float4 pre[4];
#pragma unroll
    for (int j = 0; j < 4; j++) {
        const int f  = tid + j * 256;
        const int oc = f >> 3, qd = f & 7;
        pre[j] = __ldg((const float4*)(enc1_w + (size_t)oc * FLAT + qd * 4));
    }

    for (int kci = 0; kci < NCHUNK; kci++) {
        unsigned* buf = (kci & 1) ? sW1 : sW0;
#pragma unroll
        for (int j = 0; j < 4; j++) {
            const int f  = tid + j * 256;
            const int oc = f >> 3, qd = f & 7;
            uint2 u;
            u.x = pkh2(pre[j].x, pre[j].y);
            u.y = pkh2(pre[j].z, pre[j].w);
            *(uint2*)(buf + oc * SWW + qd * 2) = u;
        }
        if (kci + 1 < NCHUNK) {
            const int kc = (kci + 1) * 32;
#pragma unroll
            for (int j = 0; j < 4; j++) {
                const int f  = tid + j * 256;
                const int oc = f >> 3, qd = f & 7;
                pre[j] = __ldg((const float4*)(enc1_w + (size_t)oc * FLAT + kc + qd * 4));
            }
        }
        __syncthreads();
        const int kw = kci * 16;               // chunk base in fp16 words
#pragma unroll
        for (int kt = 0; kt < 2; kt++) {
            unsigned a[4];
            const unsigned* ar = sC + srow * SCW + kw + kt * 8 + tig;
            a[0] = ar[0];
            a[1] = ar[8 * SCW];
            a[2] = ar[4];
            a[3] = ar[8 * SCW + 4];
#pragma unroll
            for (int nt = 0; nt < 4; nt++) {
                const unsigned* br = buf + (nbase + nt * 8 + g) * SWW + kt * 8 + tig;
                mma_fp16(c[nt], a, br[0], br[4]);
            }
        }
    }
    __syncthreads();   // all mma reads of sC done -> sH1 may overwrite it

#pragma unroll
    for (int nt = 0; nt < 4; nt++) {
        const int n0 = nbase + nt * 8 + 2 * tig;
        sH1[srow * SH1ST + n0]           = fmaxf(c[nt][0], 0.0f);
        sH1[srow * SH1ST + n0 + 1]       = fmaxf(c[nt][1], 0.0f);
        sH1[(srow + 8) * SH1ST + n0]     = fmaxf(c[nt][2], 0.0f);
        sH1[(srow + 8) * SH1ST + n0 + 1] = fmaxf(c[nt][3], 0.0f);
    }
    __syncthreads();

    // ---- enc2: [128 -> 64] -> g_theta0 transposed [dim][sample] ----
    for (int t = tid; t < ENC_SPB * HID; t += 256) {
        const int oc = t >> 5;
        const int sp = t & 31;
        float acc = __ldg(&enc2_b[oc]);
        const float* wr = enc2_w + oc * 128;
        const float* hv = sH1 + sp * SH1ST;
#pragma unroll
        for (int i = 0; i < 128; i += 4) {
            const float4 wv = __ldg((const float4*)(wr + i));
            const float4 h4 = *(const float4*)(hv + i);
            acc = fmaf(wv.x, h4.x, fmaf(wv.y, h4.y, fmaf(wv.z, h4.z, fmaf(wv.w, h4.w, acc))));
        }
        g_theta0[(size_t)oc * B + blk * ENC_SPB + sp] = acc;
    }
}

// ================================ ODE (unchanged R16) =======================
#define ODE_SPB 16
#define KW 36

__device__ __forceinline__ void gemm16h(
    const unsigned (&A)[4][4], const unsigned* __restrict__ sIn,
    float blo, float bhi, int g, int tig, float (&c)[2][4])
{
#pragma unroll
    for (int nt = 0; nt < 2; nt++) {
        c[nt][0] = blo; c[nt][1] = blo; c[nt][2] = bhi; c[nt][3] = bhi;
    }
#pragma unroll
    for (int kt = 0; kt < 4; kt++) {
#pragma unroll
        for (int nt = 0; nt < 2; nt++) {
            const unsigned* r = sIn + (nt * 8 + g) * KW + kt * 8 + tig;
            mma_fp16(c[nt], A[kt], r[0], r[4]);
        }
    }
}

__device__ __forceinline__ void store_frag_h(
    unsigned* __restrict__ dst, const float (&c)[2][4], int m0, int tig)
{
    __half* d = (__half*)dst;
#pragma unroll
    for (int nt = 0; nt < 2; nt++) {
        const int n0 = nt * 8 + 2 * tig;
        d[(n0)     * (2*KW) + m0]     = __float2half_rn(c[nt][0]);
        d[(n0 + 1) * (2*KW) + m0]     = __float2half_rn(c[nt][1]);
        d[(n0)     * (2*KW) + m0 + 8] = __float2half_rn(c[nt][2]);
        d[(n0 + 1) * (2*KW) + m0 + 8] = __float2half_rn(c[nt][3]);
    }
}

__device__ __forceinline__ void eval_fh(
    const unsigned (&A1)[4][4], const unsigned (&A2)[4][4],
    float b1lo, float b1hi, float b2lo, float b2hi,
    const unsigned* __restrict__ sY, unsigned* __restrict__ sH,
    int m0, int g, int tig, float (&k)[2][4])
{
    float h[2][4];
    gemm16h(A1, sY, b1lo, b1hi, g, tig, h);
#pragma unroll
    for (int nt = 0; nt < 2; nt++)
#pragma unroll
        for (int e = 0; e < 4; e++) h[nt][e] = tanhap(h[nt][e]);
    store_frag_h(sH, h, m0, tig);
    __syncthreads();
    gemm16h(A2, sH, b2lo, b2hi, g, tig, k);
}

__global__ void __launch_bounds__(128, 4) ode_kernel(
    const float* __restrict__ t_span,
    const float* __restrict__ w1g, const float* __restrict__ b1g,
    const float* __restrict__ w2g, const float* __restrict__ b2g,
    const float* __restrict__ r1w, const float* __restrict__ r1b,
    const float* __restrict__ r2w, const float* __restrict__ r2b,
    float* __restrict__ out, int B)
{
    __shared__ unsigned sODE[2 * ODE_SPB * KW];
    unsigned* sY = sODE;
    unsigned* sH = sODE + ODE_SPB * KW;

    const int tid  = threadIdx.x;
    const int w    = tid >> 5;
    const int lane = tid & 31;
    const int g    = lane >> 2;
    const int tig  = lane & 3;
    const int m0   = w * 16 + g;

    unsigned A1[4][4], A2[4][4];
#pragma unroll
    for (int kt = 0; kt < 4; kt++) {
        const int k0 = kt * 16 + 2 * tig;
        A1[kt][0] = pkh2(__ldg(&w1g[(m0)     * HID + k0]),     __ldg(&w1g[(m0)     * HID + k0 + 1]));
        A1[kt][1] = pkh2(__ldg(&w1g[(m0 + 8) * HID + k0]),     __ldg(&w1g[(m0 + 8) * HID + k0 + 1]));
        A1[kt][2] = pkh2(__ldg(&w1g[(m0)     * HID + k0 + 8]), __ldg(&w1g[(m0)     * HID + k0 + 9]));
        A1[kt][3] = pkh2(__ldg(&w1g[(m0 + 8) * HID + k0 + 8]), __ldg(&w1g[(m0 + 8) * HID + k0 + 9]));
        A2[kt][0] = pkh2(__ldg(&w2g[(m0)     * HID + k0]),     __ldg(&w2g[(m0)     * HID + k0 + 1]));
        A2[kt][1] = pkh2(__ldg(&w2g[(m0 + 8) * HID + k0]),     __ldg(&w2g[(m0 + 8) * HID + k0 + 1]));
        A2[kt][2] = pkh2(__ldg(&w2g[(m0)     * HID + k0 + 8]), __ldg(&w2g[(m0)     * HID + k0 + 9]));
        A2[kt][3] = pkh2(__ldg(&w2g[(m0 + 8) * HID + k0 + 8]), __ldg(&w2g[(m0 + 8) * HID + k0 + 9]));
    }
    const float b1lo = __ldg(&b1g[m0]), b1hi = __ldg(&b1g[m0 + 8]);
    const float b2lo = __ldg(&b2g[m0]), b2hi = __ldg(&b2g[m0 + 8]);

    const float dt = (__ldg(&t_span[1]) - __ldg(&t_span[0])) * (1.0f / STEPS);

    const long long gbase = (long long)blockIdx.x * ODE_SPB;
    float y[2][4];
#pragma unroll
    for (int nt = 0; nt < 2; nt++) {
        const long long n0 = gbase + nt * 8 + 2 * tig;
        y[nt][0] = __ldg(&g_theta0[(size_t)m0 * B + n0]);
        y[nt][1] = __ldg(&g_theta0[(size_t)m0 * B + n0 + 1]);
        y[nt][2] = __ldg(&g_theta0[(size_t)(m0 + 8) * B + n0]);
        y[nt][3] = __ldg(&g_theta0[(size_t)(m0 + 8) * B + n0 + 1]);
    }
    store_frag_h(sY, y, m0, tig);
    __syncthreads();

    float k1[2][4], k2[2][4], k3[2][4], k4[2][4], k5[2][4], k6[2][4], nv[2][4];

#define ELEM_LOOP(expr)                                                        \
    _Pragma("unroll") for (int nt = 0; nt < 2; nt++)                           \
    _Pragma("unroll") for (int e = 0; e < 4; e++) { expr; }

    for (int step = 0; step < STEPS; step++) {
        eval_fh(A1, A2, b1lo, b1hi, b2lo, b2hi, sY, sH, m0, g, tig, k1);
        {
            const float c1 = dt * 0.2f;
            ELEM_LOOP(nv[nt][e] = fmaf(c1, k1[nt][e], y[nt][e]));
            store_frag_h(sY, nv, m0, tig);
        }
        __syncthreads();
        eval_fh(A1, A2, b1lo, b1hi, b2lo, b2hi, sY, sH, m0, g, tig, k2);
        {
            const float c1 = dt * (3.0f / 40.0f), c2 = dt * (9.0f / 40.0f);
            ELEM_LOOP(nv[nt][e] = fmaf(c1, k1[nt][e], fmaf(c2, k2[nt][e], y[nt][e])));
            store_frag_h(sY, nv, m0, tig);
        }
        __syncthreads();
        eval_fh(A1, A2, b1lo, b1hi, b2lo, b2hi, sY, sH, m0, g, tig, k3);
        {
            const float c1 = dt * (44.0f / 45.0f), c2 = dt * (-56.0f / 15.0f),
                        c3 = dt * (32.0f / 9.0f);
            ELEM_LOOP(nv[nt][e] = fmaf(c1, k1[nt][e], fmaf(c2, k2[nt][e],
                                  fmaf(c3, k3[nt][e], y[nt][e]))));
            store_frag_h(sY, nv, m0, tig);
        }
        __syncthreads();
        eval_fh(A1, A2, b1lo, b1hi, b2lo, b2hi, sY, sH, m0, g, tig, k4);
        {
            const float c1 = dt * (19372.0f / 6561.0f), c2 = dt * (-25360.0f / 2187.0f),
                        c3 = dt * (64448.0f / 6561.0f), c4 = dt * (-212.0f / 729.0f);
            ELEM_LOOP(nv[nt][e] = fmaf(c1, k1[nt][e], fmaf(c2, k2[nt][e],
                                  fmaf(c3, k3[nt][e], fmaf(c4, k4[nt][e], y[nt][e])))));
            store_frag_h(sY, nv, m0, tig);
        }
        __syncthreads();
        eval_fh(A1, A2, b1lo, b1hi, b2lo, b2hi, sY, sH, m0, g, tig, k5);
        {
            const float c1 = dt * (9017.0f / 3168.0f), c2 = dt * (-355.0f / 33.0f),
                        c3 = dt * (46732.0f / 5247.0f), c4 = dt * (49.0f / 176.0f),
                        c5 = dt * (-5103.0f / 18656.0f);
            ELEM_LOOP(nv[nt][e] = fmaf(c1, k1[nt][e], fmaf(c2, k2[nt][e],
                                  fmaf(c3, k3[nt][e], fmaf(c4, k4[nt][e],
                                  fmaf(c5, k5[nt][e], y[nt][e]))))));
            store_frag_h(sY, nv, m0, tig);
        }
        __syncthreads();
        eval_fh(A1, A2, b1lo, b1hi, b2lo, b2hi, sY, sH, m0, g, tig, k6);
        {
            const float c1 = dt * (35.0f / 384.0f),  c3 = dt * (500.0f / 1113.0f),
                        c4 = dt * (125.0f / 192.0f), c5 = dt * (-2187.0f / 6784.0f),
                        c6 = dt * (11.0f / 84.0f);
            ELEM_LOOP(y[nt][e] = fmaf(c1, k1[nt][e], fmaf(c3, k3[nt][e],
                                 fmaf(c4, k4[nt][e], fmaf(c5, k5[nt][e],
                                 fmaf(c6, k6[nt][e], y[nt][e]))))));
            store_frag_h(sY, y, m0, tig);
        }
        __syncthreads();
    }

    {
        float* sYf = (float*)sODE;
#pragma unroll
        for (int nt = 0; nt < 2; nt++) {
            const int n0 = nt * 8 + 2 * tig;
            sYf[(n0)     * 68 + m0]     = y[nt][0];
            sYf[(n0 + 1) * 68 + m0]     = y[nt][1];
            sYf[(n0)     * 68 + m0 + 8] = y[nt][2];
            sYf[(n0 + 1) * 68 + m0 + 8] = y[nt][3];
        }
    }
    __syncthreads();

    {
        const float* sYf = (const float*)sODE;
        const int s  = tid >> 3;
        const int mg = (tid & 7) * 4;
        float accm[4];
#pragma unroll
        for (int m = 0; m < 4; m++) accm[m] = __ldg(&r1b[mg + m]);
        for (int i = 0; i < HID; i++) {
            const float yy = sYf[s * 68 + i];
#pragma unroll
            for (int m = 0; m < 4; m++)
                accm[m] = fmaf(__ldg(&r1w[(mg + m) * HID + i]), yy, accm[m]);
        }
        float part = 0.0f;
#pragma unroll
        for (int m = 0; m < 4; m++)
            part = fmaf(__ldg(&r2w[mg + m]), fmaxf(accm[m], 0.0f), part);
        part += __shfl_xor_sync(0xffffffffu, part, 1);
        part += __shfl_xor_sync(0xffffffffu, part, 2);
        part += __shfl_xor_sync(0xffffffffu, part, 4);
        if ((tid & 7) == 0)
            out[(long long)blockIdx.x * ODE_SPB + s] = part + __ldg(&r2b[0]);
    }
}

// ============================== launch ======================================
extern "C" void kernel_launch(void* const* d_in, const int* in_sizes, int n_in,
                              void* d_out, int out_size)
{
    const float* x      = (const float*)d_in[0];
    const float* t_span = (const float*)d_in[1];
    const float* conv_w = (const float*)d_in[2];
    const float* conv_b = (const float*)d_in[3];
    const float* enc1_w = (const float*)d_in[4];
    const float* enc1_b = (const float*)d_in[5];
    const float* enc2_w = (const float*)d_in[6];
    const float* enc2_b = (const float*)d_in[7];
    const float* ode1_w = (const float*)d_in[8];
    const float* ode1_b = (const float*)d_in[9];
    const float* ode2_w = (const float*)d_in[10];
    const float* ode2_b = (const float*)d_in[11];
    const float* reg1_w = (const float*)d_in[12];
    const float* reg1_b = (const float*)d_in[13];
    const float* reg2_w = (const float*)d_in[14];
    const float* reg2_b = (const float*)d_in[15];
    float* out = (float*)d_out;

    const int B = in_sizes[0] / (SEQ * INC);

    cudaFuncSetAttribute(enc_kernel, cudaFuncAttributeMaxDynamicSharedMemorySize,
                         ENC_SMEM_BYTES);

    enc_kernel<<<B / ENC_SPB, 256, ENC_SMEM_BYTES>>>(
        x, conv_w, conv_b, enc1_w, enc1_b, enc2_w, enc2_b, B);
    ode_kernel<<<B / ODE_SPB, 128>>>(
        t_span, ode1_w, ode1_b, ode2_w, ode2_b,
        reg1_w, reg1_b, reg2_w, reg2_b, out, B);
}